// round 1
// baseline (speedup 1.0000x reference)
#include <cuda_runtime.h>

#define NL 1024
#define NB 32
#define NT 12
#define NF 4
#define NH 64

// Scratch (static device globals: allocation-free rule)
__device__ float g_h[2][NL * NH * NB];      // hidden, layout [L][H][B], double buffered
__device__ float g_xT[NT * NL * NF * NB];   // x transposed to [T][L][F][B]
__device__ float g_bias[4][NL * NH];        // [0]=b_rh+b_ri, [1]=b_uh+b_ui, [2]=b_nh, [3]=b_ni ; layout [L][H]

// packed f32x2 FMA: d = a*b + c (two independent fp32 lanes, full-rate on sm_10x)
__device__ __forceinline__ float2 ffma2(float2 a, float2 b, float2 c) {
    unsigned long long ua = *reinterpret_cast<unsigned long long*>(&a);
    unsigned long long ub = *reinterpret_cast<unsigned long long*>(&b);
    unsigned long long uc = *reinterpret_cast<unsigned long long*>(&c);
    unsigned long long ud;
    asm("fma.rn.f32x2 %0, %1, %2, %3;" : "=l"(ud) : "l"(ua), "l"(ub), "l"(uc));
    return *reinterpret_cast<float2*>(&ud);
}

__device__ __forceinline__ float fsigmoid(float x) {
    return __fdividef(1.0f, 1.0f + __expf(-x));
}
__device__ __forceinline__ float ftanh_fast(float x) {
    float e = __expf(2.0f * x);                 // inf for large x -> n = 1 (correct)
    return 1.0f - __fdividef(2.0f, e + 1.0f);   // e->0 -> -1 (correct)
}

// ---------------- prep kernels ----------------

__global__ void prep_bias(const float* __restrict__ b_rh, const float* __restrict__ b_ri,
                          const float* __restrict__ b_uh, const float* __restrict__ b_ui,
                          const float* __restrict__ b_nh, const float* __restrict__ b_ni) {
    int idx = blockIdx.x * blockDim.x + threadIdx.x;   // 4 * L * H = 262144
    if (idx >= 4 * NL * NH) return;
    int q = idx >> 16;           // which bias set
    int r = idx & 65535;         // l*64 + k
    int l = r >> 6;
    int k = r & 63;
    int src = k * NL + l;        // biases are [H][L]
    float v;
    if (q == 0)      v = b_rh[src] + b_ri[src];
    else if (q == 1) v = b_uh[src] + b_ui[src];
    else if (q == 2) v = b_nh[src];
    else             v = b_ni[src];
    g_bias[q][r] = v;
}

__global__ void prep_x(const float* __restrict__ x) {
    int idx = blockIdx.x * blockDim.x + threadIdx.x;   // T*L*F*B = 1572864
    if (idx >= NT * NL * NF * NB) return;
    int b = idx & 31;
    int f = (idx >> 5) & 3;
    int l = (idx >> 7) & 1023;
    int t = idx >> 17;
    g_xT[idx] = x[((b * NT + t) * NF + f) * NL + l];
}

// ---------------- GRU step kernel ----------------
// block = link l, 128 threads. Thread tile: 4 b x 4 k, all 3 gates (48 accumulators).
// k-paired float2 accumulators so the weight operand of fma.f32x2 loads directly.

template <bool FIRST>
__global__ void __launch_bounds__(128, 4)
step_kernel(const float* __restrict__ att,
            const float* __restrict__ w_rh, const float* __restrict__ w_uh, const float* __restrict__ w_nh,
            const float* __restrict__ w_ri, const float* __restrict__ w_ui, const float* __restrict__ w_ni,
            int t, int cur, int nxt) {
    __shared__ float sW[3 * 32 * 64];   // half of the gate weights: [g][h'][k]
    __shared__ float sHatt[64 * 32];    // [h][b]
    __shared__ float sXt[NF * NB];      // [f][b]
    __shared__ float sWi[3 * NF * NH];  // [g][f][k]
    __shared__ float sBs[4 * NH];       // combined biases [q][k]

    const int l   = blockIdx.x;
    const int tid = threadIdx.x;
    const int kgrp = tid & 15;     // 16 k-groups
    const int bgrp = tid >> 4;     // 8 b-groups
    const int k0 = kgrp * 4;
    const int b0 = bgrp * 4;

    // --- stage small per-link data ---
    sXt[tid] = g_xT[(t * NL + l) * (NF * NB) + tid];
    {
        int i0 = tid, i1 = tid + 128;
        sWi[i0]       = w_ri[l * 256 + i0];
        sWi[i1]       = w_ri[l * 256 + i1];
        sWi[256 + i0] = w_ui[l * 256 + i0];
        sWi[256 + i1] = w_ui[l * 256 + i1];
        sWi[512 + i0] = w_ni[l * 256 + i0];
        sWi[512 + i1] = w_ni[l * 256 + i1];
        sBs[i0] = g_bias[i0 >> 6][l * 64 + (i0 & 63)];
        sBs[i1] = g_bias[i1 >> 6][l * 64 + (i1 & 63)];
    }

    if (!FIRST) {
        // graph attention: banded mix of neighbor hidden states (coeffs read from matrix)
        float a0 = att[l * NL + l];
        float am = (l > 0)      ? att[l * NL + l - 1] : 0.0f;
        float ap = (l < NL - 1) ? att[l * NL + l + 1] : 0.0f;
        const int lm = (l > 0) ? l - 1 : l;
        const int lp = (l < NL - 1) ? l + 1 : l;
        const float4* hm = (const float4*)(g_h[cur] + lm * (NH * NB));
        const float4* hc = (const float4*)(g_h[cur] + l  * (NH * NB));
        const float4* hp = (const float4*)(g_h[cur] + lp * (NH * NB));
        float4* sh = (float4*)sHatt;
#pragma unroll
        for (int i = 0; i < 4; i++) {
            int j = tid + i * 128;
            float4 m = hm[j], c = hc[j], p = hp[j];
            float4 v;
            v.x = am * m.x + a0 * c.x + ap * p.x;
            v.y = am * m.y + a0 * c.y + ap * p.y;
            v.z = am * m.z + a0 * c.z + ap * p.z;
            v.w = am * m.w + a0 * c.w + ap * p.w;
            sh[j] = v;
        }
        // weights half 0 (h rows 0..31)
        {
            const float4* wr = (const float4*)(w_rh + l * 4096);
            const float4* wu = (const float4*)(w_uh + l * 4096);
            const float4* wn = (const float4*)(w_nh + l * 4096);
            float4* dW = (float4*)sW;
#pragma unroll
            for (int i = 0; i < 4; i++) {
                int j = tid + i * 128;
                dW[j]        = wr[j];
                dW[512 + j]  = wu[j];
                dW[1024 + j] = wn[j];
            }
        }
    }
    __syncthreads();

    // --- accumulator init: biases + input-feature GEMM (F=4) ---
    // float2 pairing over k: acc2[b*2 + kp] covers (b0+b, k0+2kp .. +1).
    // flat float index = b*4 + kk  (kk = 2*kp + half)
    float2 aR2[8], aZ2[8], aN2[8];
    float* accR = (float*)aR2;
    float* accZ = (float*)aZ2;
    float* accNH = (float*)aN2;
    float xiN[16];
#pragma unroll
    for (int bb = 0; bb < 4; bb++) {
        float xv[4];
#pragma unroll
        for (int f = 0; f < 4; f++) xv[f] = sXt[f * 32 + b0 + bb];
#pragma unroll
        for (int kk = 0; kk < 4; kk++) {
            int k = k0 + kk;
            float r = sBs[k], z = sBs[64 + k], ni = sBs[192 + k];
#pragma unroll
            for (int f = 0; f < 4; f++) {
                r  += xv[f] * sWi[f * 64 + k];
                z  += xv[f] * sWi[256 + f * 64 + k];
                ni += xv[f] * sWi[512 + f * 64 + k];
            }
            accR[bb * 4 + kk] = r;
            accZ[bb * 4 + kk] = z;
            accNH[bb * 4 + kk] = sBs[128 + k];  // b_nh (inside r*(...))
            xiN[bb * 4 + kk] = ni;              // b_ni + x-part (outside)
        }
    }

    if (!FIRST) {
        // --- main hidden GEMM, two halves of 32 h-rows each ---
        auto gemm_half = [&](int hbase) {
#pragma unroll 4
            for (int hh = 0; hh < 32; hh++) {
                float4 hv = *(const float4*)&sHatt[(hbase + hh) * 32 + b0];
                float2 hb[4] = { {hv.x, hv.x}, {hv.y, hv.y}, {hv.z, hv.z}, {hv.w, hv.w} };
#pragma unroll
                for (int kp = 0; kp < 2; kp++) {
                    float2 wr = *(const float2*)&sW[hh * 64 + k0 + 2 * kp];
                    float2 wu = *(const float2*)&sW[2048 + hh * 64 + k0 + 2 * kp];
                    float2 wn = *(const float2*)&sW[4096 + hh * 64 + k0 + 2 * kp];
#pragma unroll
                    for (int bb = 0; bb < 4; bb++) {
                        aR2[bb * 2 + kp] = ffma2(hb[bb], wr, aR2[bb * 2 + kp]);
                        aZ2[bb * 2 + kp] = ffma2(hb[bb], wu, aZ2[bb * 2 + kp]);
                        aN2[bb * 2 + kp] = ffma2(hb[bb], wn, aN2[bb * 2 + kp]);
                    }
                }
            }
        };
        gemm_half(0);
        __syncthreads();
        // weights half 1 (h rows 32..63)
        {
            const float4* wr = (const float4*)(w_rh + l * 4096 + 2048);
            const float4* wu = (const float4*)(w_uh + l * 4096 + 2048);
            const float4* wn = (const float4*)(w_nh + l * 4096 + 2048);
            float4* dW = (float4*)sW;
#pragma unroll
            for (int i = 0; i < 4; i++) {
                int j = tid + i * 128;
                dW[j]        = wr[j];
                dW[512 + j]  = wu[j];
                dW[1024 + j] = wn[j];
            }
        }
        __syncthreads();
        gemm_half(32);
    }

    // --- GRU epilogue + write h_next ([L][H][B], coalesced float4) ---
    const float* hcur = g_h[cur] + l * (NH * NB);
    float* hnxt = g_h[nxt] + l * (NH * NB);
#pragma unroll
    for (int kk = 0; kk < 4; kk++) {
        int k = k0 + kk;
        float holdv[4] = {0.f, 0.f, 0.f, 0.f};
        if (!FIRST) {
            float4 h4 = *(const float4*)&hcur[k * 32 + b0];
            holdv[0] = h4.x; holdv[1] = h4.y; holdv[2] = h4.z; holdv[3] = h4.w;
        }
        float o[4];
#pragma unroll
        for (int bb = 0; bb < 4; bb++) {
            int p = bb * 4 + kk;
            float r = fsigmoid(accR[p]);
            float z = fsigmoid(accZ[p]);
            float n = ftanh_fast(xiN[p] + r * accNH[p]);
            o[bb] = n + z * (holdv[bb] - n);
        }
        *(float4*)&hnxt[k * 32 + b0] = make_float4(o[0], o[1], o[2], o[3]);
    }
}

// ---------------- output head ----------------
__global__ void fc_kernel(const float* __restrict__ w_fc, const float* __restrict__ b_fc,
                          float* __restrict__ out) {
    int l = blockIdx.x;
    int b = threadIdx.x;   // 32 threads
    const float* h = g_h[0] + l * (NH * NB);
    float acc = b_fc[l];
#pragma unroll 8
    for (int k = 0; k < NH; k++) acc += h[k * 32 + b] * w_fc[l * NH + k];
    out[b * NL + l] = acc;   // [B][O=1][L]
}

// ---------------- launch ----------------
extern "C" void kernel_launch(void* const* d_in, const int* in_sizes, int n_in,
                              void* d_out, int out_size) {
    const float* x    = (const float*)d_in[0];
    const float* att  = (const float*)d_in[1];
    const float* w_rh = (const float*)d_in[2];
    const float* b_rh = (const float*)d_in[3];
    const float* w_ri = (const float*)d_in[4];
    const float* b_ri = (const float*)d_in[5];
    const float* w_uh = (const float*)d_in[6];
    const float* b_uh = (const float*)d_in[7];
    const float* w_ui = (const float*)d_in[8];
    const float* b_ui = (const float*)d_in[9];
    const float* w_nh = (const float*)d_in[10];
    const float* b_nh = (const float*)d_in[11];
    const float* w_ni = (const float*)d_in[12];
    const float* b_ni = (const float*)d_in[13];
    const float* w_fc = (const float*)d_in[14];
    const float* b_fc = (const float*)d_in[15];

    prep_bias<<<1024, 256>>>(b_rh, b_ri, b_uh, b_ui, b_nh, b_ni);
    prep_x<<<6144, 256>>>(x);

    // t=0: h=0, skip attention + hidden GEMM
    step_kernel<true><<<1024, 128>>>(att, w_rh, w_uh, w_nh, w_ri, w_ui, w_ni, 0, 0, 1);
    for (int t = 1; t < NT; t++) {
        step_kernel<false><<<1024, 128>>>(att, w_rh, w_uh, w_nh, w_ri, w_ui, w_ni,
                                          t, t & 1, (t + 1) & 1);
    }
    // after t=11 (writes buffer 0)
    fc_kernel<<<1024, 32>>>(w_fc, b_fc, (float*)d_out);
}

// round 3
// speedup vs baseline: 1.1200x; 1.1200x over previous
#include <cuda_runtime.h>
#include <cstdint>

#define NL 1024
#define NB 32
#define NT 12
#define NF 4
#define NH 64

// Scratch (static device globals: allocation-free rule)
__device__ float g_h[2][NL * NH * NB];      // hidden, layout [L][H][B], double buffered
__device__ float g_xT[NT * NL * NF * NB];   // x transposed to [T][L][F][B]
__device__ float g_bias[4][NL * NH];        // [0]=b_rh+b_ri, [1]=b_uh+b_ui, [2]=b_nh, [3]=b_ni ; layout [L][H]

// packed f32x2 FMA: d = a*b + c (two independent fp32 lanes, full-rate on sm_10x)
__device__ __forceinline__ float2 ffma2(float2 a, float2 b, float2 c) {
    unsigned long long ua = *reinterpret_cast<unsigned long long*>(&a);
    unsigned long long ub = *reinterpret_cast<unsigned long long*>(&b);
    unsigned long long uc = *reinterpret_cast<unsigned long long*>(&c);
    unsigned long long ud;
    asm("fma.rn.f32x2 %0, %1, %2, %3;" : "=l"(ud) : "l"(ua), "l"(ub), "l"(uc));
    return *reinterpret_cast<float2*>(&ud);
}

__device__ __forceinline__ void cp16(uint32_t dst, const void* src) {
    asm volatile("cp.async.cg.shared.global [%0], [%1], 16;\n" :: "r"(dst), "l"(src));
}
__device__ __forceinline__ void cp_commit() {
    asm volatile("cp.async.commit_group;\n" ::: "memory");
}
template <int N>
__device__ __forceinline__ void cp_wait() {
    asm volatile("cp.async.wait_group %0;\n" :: "n"(N) : "memory");
}

__device__ __forceinline__ float fsigmoid(float x) {
    return __fdividef(1.0f, 1.0f + __expf(-x));
}
__device__ __forceinline__ float ftanh_fast(float x) {
    float e = __expf(2.0f * x);                 // inf for large x -> n = 1 (correct)
    return 1.0f - __fdividef(2.0f, e + 1.0f);   // e->0 -> -1 (correct)
}

// ---------------- prep kernels ----------------

__global__ void prep_bias(const float* __restrict__ b_rh, const float* __restrict__ b_ri,
                          const float* __restrict__ b_uh, const float* __restrict__ b_ui,
                          const float* __restrict__ b_nh, const float* __restrict__ b_ni) {
    int idx = blockIdx.x * blockDim.x + threadIdx.x;   // 4 * L * H = 262144
    if (idx >= 4 * NL * NH) return;
    int q = idx >> 16;           // which bias set
    int r = idx & 65535;         // l*64 + k
    int l = r >> 6;
    int k = r & 63;
    int src = k * NL + l;        // biases are [H][L]
    float v;
    if (q == 0)      v = b_rh[src] + b_ri[src];
    else if (q == 1) v = b_uh[src] + b_ui[src];
    else if (q == 2) v = b_nh[src];
    else             v = b_ni[src];
    g_bias[q][r] = v;
}

__global__ void prep_x(const float* __restrict__ x) {
    int idx = blockIdx.x * blockDim.x + threadIdx.x;   // T*L*F*B = 1572864
    if (idx >= NT * NL * NF * NB) return;
    int b = idx & 31;
    int f = (idx >> 5) & 3;
    int l = (idx >> 7) & 1023;
    int t = idx >> 17;
    g_xT[idx] = x[((b * NT + t) * NF + f) * NL + l];
}

// ---------------- GRU step kernel ----------------
// block = link l, 128 threads. Thread tile: 4 b x 4 k, all 3 gates (48 accumulators).
// All 48KB of gate weights preloaded via cp.async in two groups (double-buffered halves),
// so the hidden GEMM never waits on a mid-kernel reload.
// Dynamic smem layout: [0 .. 12288) weights [g][h][k]; [12288 .. 14336) hatt [h][b].

template <bool FIRST>
__global__ void __launch_bounds__(128, 4)
step_kernel(const float* __restrict__ att,
            const float* __restrict__ w_rh, const float* __restrict__ w_uh, const float* __restrict__ w_nh,
            const float* __restrict__ w_ri, const float* __restrict__ w_ui, const float* __restrict__ w_ni,
            int t, int cur, int nxt) {
    extern __shared__ float smem[];
    float* sW = smem;              // [3][64][64]
    float* sHatt = smem + 12288;   // [64][32]

    const int l   = blockIdx.x;
    const int tid = threadIdx.x;
    const int kgrp = tid & 15;     // 16 k-groups
    const int bgrp = tid >> 4;     // 8 b-groups
    const int k0 = kgrp * 4;
    const int b0 = bgrp * 4;

    if (!FIRST) {
        // ---- issue weight copies first so latency overlaps hatt work ----
        uint32_t swb = (uint32_t)__cvta_generic_to_shared(sW);
#pragma unroll
        for (int hf = 0; hf < 2; hf++) {
            {
                const float4* src = (const float4*)(w_rh + l * 4096 + hf * 2048);
                uint32_t dstb = swb + (uint32_t)(hf * 2048) * 4u;
#pragma unroll
                for (int i = 0; i < 4; i++) { int j = tid + i * 128; cp16(dstb + j * 16, src + j); }
            }
            {
                const float4* src = (const float4*)(w_uh + l * 4096 + hf * 2048);
                uint32_t dstb = swb + (uint32_t)(4096 + hf * 2048) * 4u;
#pragma unroll
                for (int i = 0; i < 4; i++) { int j = tid + i * 128; cp16(dstb + j * 16, src + j); }
            }
            {
                const float4* src = (const float4*)(w_nh + l * 4096 + hf * 2048);
                uint32_t dstb = swb + (uint32_t)(8192 + hf * 2048) * 4u;
#pragma unroll
                for (int i = 0; i < 4; i++) { int j = tid + i * 128; cp16(dstb + j * 16, src + j); }
            }
            cp_commit();
        }

        // ---- graph attention: banded mix of neighbor hidden states ----
        float a0 = att[l * NL + l];
        float am = (l > 0)      ? att[l * NL + l - 1] : 0.0f;
        float ap = (l < NL - 1) ? att[l * NL + l + 1] : 0.0f;
        const int lm = (l > 0) ? l - 1 : l;
        const int lp = (l < NL - 1) ? l + 1 : l;
        const float4* hm = (const float4*)(g_h[cur] + lm * (NH * NB));
        const float4* hc = (const float4*)(g_h[cur] + l  * (NH * NB));
        const float4* hp = (const float4*)(g_h[cur] + lp * (NH * NB));
        float4* sh = (float4*)sHatt;
#pragma unroll
        for (int i = 0; i < 4; i++) {
            int j = tid + i * 128;
            float4 m = hm[j], c = hc[j], p = hp[j];
            float4 v;
            v.x = am * m.x + a0 * c.x + ap * p.x;
            v.y = am * m.y + a0 * c.y + ap * p.y;
            v.z = am * m.z + a0 * c.z + ap * p.z;
            v.w = am * m.w + a0 * c.w + ap * p.w;
            sh[j] = v;
        }
    }

    // --- accumulator init: biases + input-feature GEMM (F=4), all via direct LDG ---
    // float2 pairing over k: acc2[b*2 + kp] covers (b0+b, k0+2kp .. +1).
    // flat float index = b*4 + kk  (kk = 2*kp + half)
    float2 aR2[8], aZ2[8], aN2[8], xiN2[8];
    float* accR  = (float*)aR2;
    float* accZ  = (float*)aZ2;
    float* accNH = (float*)aN2;
    float* xiN   = (float*)xiN2;
    {
        // biases
        float4 br = *(const float4*)&g_bias[0][l * 64 + k0];
        float4 bz = *(const float4*)&g_bias[1][l * 64 + k0];
        float4 bh = *(const float4*)&g_bias[2][l * 64 + k0];
        float4 bn = *(const float4*)&g_bias[3][l * 64 + k0];
#pragma unroll
        for (int bb = 0; bb < 4; bb++) {
            aR2[bb * 2 + 0] = make_float2(br.x, br.y);  aR2[bb * 2 + 1] = make_float2(br.z, br.w);
            aZ2[bb * 2 + 0] = make_float2(bz.x, bz.y);  aZ2[bb * 2 + 1] = make_float2(bz.z, bz.w);
            aN2[bb * 2 + 0] = make_float2(bh.x, bh.y);  aN2[bb * 2 + 1] = make_float2(bh.z, bh.w);
            xiN2[bb * 2 + 0] = make_float2(bn.x, bn.y); xiN2[bb * 2 + 1] = make_float2(bn.z, bn.w);
        }
        // x part: F=4. x layout [t][l][f][b]; weights [l][f][k].
        const float* xb = g_xT + (t * NL + l) * (NF * NB);
#pragma unroll
        for (int f = 0; f < 4; f++) {
            float4 xv = *(const float4*)&xb[f * 32 + b0];           // 4 b's
            float2 xs[4] = { {xv.x, xv.x}, {xv.y, xv.y}, {xv.z, xv.z}, {xv.w, xv.w} };
            float4 wr = *(const float4*)&w_ri[l * 256 + f * 64 + k0];
            float4 wu = *(const float4*)&w_ui[l * 256 + f * 64 + k0];
            float4 wn = *(const float4*)&w_ni[l * 256 + f * 64 + k0];
            float2 wr0 = make_float2(wr.x, wr.y), wr1 = make_float2(wr.z, wr.w);
            float2 wu0 = make_float2(wu.x, wu.y), wu1 = make_float2(wu.z, wu.w);
            float2 wn0 = make_float2(wn.x, wn.y), wn1 = make_float2(wn.z, wn.w);
#pragma unroll
            for (int bb = 0; bb < 4; bb++) {
                aR2[bb * 2 + 0] = ffma2(xs[bb], wr0, aR2[bb * 2 + 0]);
                aR2[bb * 2 + 1] = ffma2(xs[bb], wr1, aR2[bb * 2 + 1]);
                aZ2[bb * 2 + 0] = ffma2(xs[bb], wu0, aZ2[bb * 2 + 0]);
                aZ2[bb * 2 + 1] = ffma2(xs[bb], wu1, aZ2[bb * 2 + 1]);
                xiN2[bb * 2 + 0] = ffma2(xs[bb], wn0, xiN2[bb * 2 + 0]);
                xiN2[bb * 2 + 1] = ffma2(xs[bb], wn1, xiN2[bb * 2 + 1]);
            }
        }
    }

    if (!FIRST) {
        // --- main hidden GEMM, two halves of 32 h-rows each, overlapped with cp.async ---
        auto gemm_half = [&](int hbase) {
#pragma unroll 8
            for (int hh = 0; hh < 32; hh++) {
                const int hr = hbase + hh;
                float4 hv = *(const float4*)&sHatt[hr * 32 + b0];
                float2 hb[4] = { {hv.x, hv.x}, {hv.y, hv.y}, {hv.z, hv.z}, {hv.w, hv.w} };
                float4 wr = *(const float4*)&sW[hr * 64 + k0];
                float4 wu = *(const float4*)&sW[4096 + hr * 64 + k0];
                float4 wn = *(const float4*)&sW[8192 + hr * 64 + k0];
                float2 wr0 = make_float2(wr.x, wr.y), wr1 = make_float2(wr.z, wr.w);
                float2 wu0 = make_float2(wu.x, wu.y), wu1 = make_float2(wu.z, wu.w);
                float2 wn0 = make_float2(wn.x, wn.y), wn1 = make_float2(wn.z, wn.w);
#pragma unroll
                for (int bb = 0; bb < 4; bb++) {
                    aR2[bb * 2 + 0] = ffma2(hb[bb], wr0, aR2[bb * 2 + 0]);
                    aR2[bb * 2 + 1] = ffma2(hb[bb], wr1, aR2[bb * 2 + 1]);
                    aZ2[bb * 2 + 0] = ffma2(hb[bb], wu0, aZ2[bb * 2 + 0]);
                    aZ2[bb * 2 + 1] = ffma2(hb[bb], wu1, aZ2[bb * 2 + 1]);
                    aN2[bb * 2 + 0] = ffma2(hb[bb], wn0, aN2[bb * 2 + 0]);
                    aN2[bb * 2 + 1] = ffma2(hb[bb], wn1, aN2[bb * 2 + 1]);
                }
            }
        };
        cp_wait<1>();          // half 0 landed
        __syncthreads();       // hatt + half-0 weights visible to all
        gemm_half(0);
        cp_wait<0>();          // half 1 landed (copied while gemm_half(0) ran)
        __syncthreads();
        gemm_half(32);
    }

    // --- GRU epilogue + write h_next ([L][H][B], coalesced float4) ---
    const float* hcur = g_h[cur] + l * (NH * NB);
    float* hnxt = g_h[nxt] + l * (NH * NB);
#pragma unroll
    for (int kk = 0; kk < 4; kk++) {
        int k = k0 + kk;
        float holdv[4] = {0.f, 0.f, 0.f, 0.f};
        if (!FIRST) {
            float4 h4 = *(const float4*)&hcur[k * 32 + b0];
            holdv[0] = h4.x; holdv[1] = h4.y; holdv[2] = h4.z; holdv[3] = h4.w;
        }
        float o[4];
#pragma unroll
        for (int bb = 0; bb < 4; bb++) {
            int p = bb * 4 + kk;
            float r = fsigmoid(accR[p]);
            float z = fsigmoid(accZ[p]);
            float n = ftanh_fast(xiN[p] + r * accNH[p]);
            o[bb] = n + z * (holdv[bb] - n);
        }
        *(float4*)&hnxt[k * 32 + b0] = make_float4(o[0], o[1], o[2], o[3]);
    }
}

// ---------------- output head ----------------
__global__ void fc_kernel(const float* __restrict__ w_fc, const float* __restrict__ b_fc,
                          float* __restrict__ out) {
    int l = blockIdx.x;
    int b = threadIdx.x;   // 32 threads
    const float* h = g_h[0] + l * (NH * NB);
    float acc = b_fc[l];
#pragma unroll 8
    for (int k = 0; k < NH; k++) acc += h[k * 32 + b] * w_fc[l * NH + k];
    out[b * NL + l] = acc;   // [B][O=1][L]
}

// ---------------- launch ----------------
#define STEP_SMEM (14336 * 4)   // 56 KB: 48KB weights + 8KB hatt

static void configure_attrs_once() {
    // Runs on the first kernel_launch call (the harness's correctness run,
    // which precedes graph capture). cudaFuncSetAttribute is not legal inside
    // stream capture, so it must not execute on the capture call.
    static bool done = false;
    if (done) return;
    cudaFuncSetAttribute(step_kernel<true>,  cudaFuncAttributeMaxDynamicSharedMemorySize, STEP_SMEM);
    cudaFuncSetAttribute(step_kernel<false>, cudaFuncAttributeMaxDynamicSharedMemorySize, STEP_SMEM);
    done = true;
}

extern "C" void kernel_launch(void* const* d_in, const int* in_sizes, int n_in,
                              void* d_out, int out_size) {
    const float* x    = (const float*)d_in[0];
    const float* att  = (const float*)d_in[1];
    const float* w_rh = (const float*)d_in[2];
    const float* b_rh = (const float*)d_in[3];
    const float* w_ri = (const float*)d_in[4];
    const float* b_ri = (const float*)d_in[5];
    const float* w_uh = (const float*)d_in[6];
    const float* b_uh = (const float*)d_in[7];
    const float* w_ui = (const float*)d_in[8];
    const float* b_ui = (const float*)d_in[9];
    const float* w_nh = (const float*)d_in[10];
    const float* b_nh = (const float*)d_in[11];
    const float* w_ni = (const float*)d_in[12];
    const float* b_ni = (const float*)d_in[13];
    const float* w_fc = (const float*)d_in[14];
    const float* b_fc = (const float*)d_in[15];

    configure_attrs_once();

    prep_bias<<<1024, 256>>>(b_rh, b_ri, b_uh, b_ui, b_nh, b_ni);
    prep_x<<<6144, 256>>>(x);

    // t=0: h=0, skip attention + hidden GEMM
    step_kernel<true><<<1024, 128, STEP_SMEM>>>(att, w_rh, w_uh, w_nh, w_ri, w_ui, w_ni, 0, 0, 1);
    for (int t = 1; t < NT; t++) {
        step_kernel<false><<<1024, 128, STEP_SMEM>>>(att, w_rh, w_uh, w_nh, w_ri, w_ui, w_ni,
                                                     t, t & 1, (t + 1) & 1);
    }
    // after t=11 (writes buffer 0)
    fc_kernel<<<1024, 32>>>(w_fc, b_fc, (float*)d_out);
}